// round 12
// baseline (speedup 1.0000x reference)
#include <cuda_runtime.h>
#include <cuda_fp16.h>

// ---------------- problem constants ----------------
#define NBLK 32
#define NTHR 1024
#define LPn  128
#define Bn   64

// packed-weight tile grids (16k x 8j tiles, B-fragment order)
#define WV_NCH  10
#define WV_NJT  20
#define WHH_NCH 10
#define WHH_NJT 58
#define WGC_NCH 10
#define WGC_NJT 75
#define WIH_NCH 40
#define WIH_NJT 58

// ---------------- device scratch ----------------
__device__ float d_WpE[150 * 152];
__device__ float d_WqE[150 * 152];
__device__ float d_WgU[600 * 152];
__device__ uint2 g_WvPk [WV_NCH  * WV_NJT  * 32];   // Wv^T    (k x j=150)
__device__ uint2 g_WhhPk[WHH_NCH * WHH_NJT * 32];   // W_hh^T  (k x j=450)
__device__ uint2 g_WgCPk[WGC_NCH * WGC_NJT * 32];   // WgC^T   (k x j=600)
__device__ uint2 g_WihPk[WIH_NCH * WIH_NJT * 32];   // W_ih^T  (k=600 x j=450)
__device__ float d_wup[Bn * LPn * 150];
__device__ float d_gu [Bn * LPn * 600];
__device__ unsigned g_flags[NBLK];
__device__ unsigned g_rel2;

// ---------------- smem layout (float slots) ----------------
// UQH:  2 x (128x152 halfs)  = 19456 slots   (Uq fp16, per batch)
// WUQH: 2 x (128x154 halfs)  = 19712 slots   (Wuq fp16, stride 154 halfs;
//                                             P1 phase-1 fp32 Up staging aliases here)
// SCR:  2 x SCB per-batch scratch
#define UQH_S   0
#define WUQH_S  19456
#define SCR     39168
#define SCB     6016
// per-batch scratch offsets (relative)
#define R_V    0      // 152
#define R_VB   152    // 152
#define R_U    304    // 152
#define R_BSE  456    // 152
#define R_CC   608    // 152
#define R_A    760    // 128 softmax result
#define R_GU   888    // 600
#define R_GH   1488   // 464
#define R_VP   1952   // 80  (uint pairs of v, k pad 160)
#define R_CP2  2032   // 80  (uint pairs of cc)
#define R_RGP  2112   // 320 (uint pairs of rg, k pad 640)
#define R_WVP  2432   // 2 x 160 wv partials
#define R_BP   2752   // 2 x 600 B partials
#define R_CPP  3952   // 2 x 464 C partials
#define R_CCP  4880   // 4 x 152 cc partials
#define R_AP   5488   // 512 s partials (4 k-groups x 128 l)
#define SMEM_FL (SCR + 2 * SCB)          // 51200 floats
#define SMEM_BYTES (SMEM_FL * 4)         // 204800 B

// ---------------- helpers ----------------
__device__ __forceinline__ float warp_max_all(float v) {
#pragma unroll
    for (int o = 16; o > 0; o >>= 1) v = fmaxf(v, __shfl_xor_sync(0xffffffffu, v, o));
    return v;
}
__device__ __forceinline__ float warp_sum_all(float v) {
#pragma unroll
    for (int o = 16; o > 0; o >>= 1) v += __shfl_xor_sync(0xffffffffu, v, o);
    return v;
}
__device__ __forceinline__ float fast_sig(float x) {
    return 1.0f / (1.0f + __expf(-x));
}
__device__ __forceinline__ float fast_tanh(float x) {
    float cx = fminf(fmaxf(x, -15.0f), 15.0f);
    float e  = __expf(2.0f * cx);
    return __fdividef(e - 1.0f, e + 1.0f);
}
__device__ __forceinline__ float tanh_fastest(float x) {
    float y;
    asm("tanh.approx.f32 %0, %1;" : "=f"(y) : "f"(x));
    return y;
}
__device__ __forceinline__ unsigned pack2(float x, float y) {
    __half2 h = __floats2half2_rn(x, y);
    return *reinterpret_cast<unsigned*>(&h);
}

// m16n8k16 f16 MMA, f32 accumulate, DUAL-batch GEMV:
// A row 0 = batch0 x (a0/a2), A row 8 = batch1 x (a1/a3), other rows zero.
// D: {d0,d1} = batch0 j-pair (row 0), {d2,d3} = batch1 j-pair (row 8).
__device__ __forceinline__ void mma2(float* d, unsigned a0, unsigned a1,
                                     unsigned a2, unsigned a3,
                                     unsigned b0, unsigned b1) {
    asm volatile(
        "mma.sync.aligned.m16n8k16.row.col.f32.f16.f16.f32 "
        "{%0,%1,%2,%3}, {%4,%5,%6,%7}, {%8,%9}, {%0,%1,%2,%3};"
        : "+f"(d[0]), "+f"(d[1]), "+f"(d[2]), "+f"(d[3])
        : "r"(a0), "r"(a1), "r"(a2), "r"(a3), "r"(b0), "r"(b1));
}

// Dual-batch GEMV tile loop: NT j-tiles over chunks [kc0,kc1).
template<int NT>
__device__ __forceinline__ void gemv2(float d[][4], const uint2* __restrict__ Wpk,
                                      int njt, int kc0, int kc1, int jt0,
                                      const unsigned* __restrict__ xp0,
                                      const unsigned* __restrict__ xp1, int ln) {
    for (int kc = kc0; kc < kc1; kc++) {
        unsigned a0 = 0, a1 = 0, a2 = 0, a3 = 0;
        if (ln < 4) {
            a0 = xp0[kc * 8 + ln];     a1 = xp1[kc * 8 + ln];
            a2 = xp0[kc * 8 + 4 + ln]; a3 = xp1[kc * 8 + 4 + ln];
        }
        const uint2* wr = Wpk + (kc * njt + jt0) * 32 + ln;
#pragma unroll
        for (int t = 0; t < NT; t++) {
            uint2 bb = __ldg(&wr[t * 32]);
            mma2(d[t], a0, a1, a2, a3, bb.x, bb.y);
        }
    }
}
template<int NT>
__device__ __forceinline__ void store2(const float d[][4], float* dst0, float* dst1,
                                       int jt0, int ln) {
    if (ln < 4) {
#pragma unroll
        for (int t = 0; t < NT; t++) {
            *(float2*)(dst0 + (jt0 + t) * 8 + 2 * ln) = make_float2(d[t][0], d[t][1]);
            *(float2*)(dst1 + (jt0 + t) * 8 + 2 * ln) = make_float2(d[t][2], d[t][3]);
        }
    }
}
// gh variant: bounded direct store with bias
template<int NT>
__device__ __forceinline__ void store2_gh(const float d[][4], float* gh0, float* gh1,
                                          int jt0, int ln,
                                          const float* __restrict__ b_hh) {
    if (ln < 4) {
#pragma unroll
        for (int t = 0; t < NT; t++) {
            int j = (jt0 + t) * 8 + 2 * ln;
            if (j < 450) {
                float bb0 = b_hh[j], bb1 = b_hh[j + 1];
                gh0[j] = d[t][0] + bb0; gh0[j + 1] = d[t][1] + bb1;
                gh1[j] = d[t][2] + bb0; gh1[j + 1] = d[t][3] + bb1;
            }
        }
    }
}

// Flag-array grid barrier (prologue only). Monotonic, atomic-free.
__device__ __forceinline__ void gsync(unsigned& gen) {
    __syncthreads();
    const unsigned target = gen + 1u;
    if (blockIdx.x == 0) {
        if (threadIdx.x < 32) {
            const int ln = threadIdx.x;
            if (ln == 0) *((volatile unsigned*)&g_flags[0]) = target;
            bool ok;
            do {
                unsigned f0;
                asm volatile("ld.acquire.gpu.u32 %0, [%1];" : "=r"(f0) : "l"(&g_flags[ln]));
                ok = (f0 >= target);
            } while (!__all_sync(0xffffffffu, ok));
            if (ln == 0)
                asm volatile("st.release.gpu.u32 [%0], %1;" :: "l"(&g_rel2), "r"(target) : "memory");
        }
    } else {
        if (threadIdx.x == 0) {
            asm volatile("st.release.gpu.u32 [%0], %1;"
                         :: "l"(&g_flags[blockIdx.x]), "r"(target) : "memory");
            unsigned r;
            do {
                asm volatile("ld.acquire.gpu.u32 %0, [%1];" : "=r"(r) : "l"(&g_rel2));
            } while (r < target);
        }
    }
    gen = target;
    __syncthreads();
}

// ---------------- the persistent kernel: one block per TWO batches ----------------
__global__ void __launch_bounds__(NTHR, 1) pqm_kernel(
    const float* __restrict__ Up, const float* __restrict__ Uq,
    const float* __restrict__ Wp, const float* __restrict__ Wq,
    const float* __restrict__ Wv, const float* __restrict__ Wg,
    const float* __restrict__ Vmat, const float* __restrict__ v0,
    const float* __restrict__ W_ih, const float* __restrict__ W_hh,
    const float* __restrict__ b_ih, const float* __restrict__ b_hh,
    float* __restrict__ out)
{
    extern __shared__ float sm[];
    __half* UQH  = (__half*)(sm + UQH_S);    // + bb*19456 halfs
    __half* WUQH = (__half*)(sm + WUQH_S);   // + bb*19712 halfs
    const int tid = threadIdx.x;
    const int blk = blockIdx.x;
    const int w   = tid >> 5, ln = tid & 31;

    unsigned gen = *((volatile unsigned*)&g_rel2);

    // ======== P0: folds + packed fp16 B-fragment weight builds ========
    const int gid = blk * NTHR + tid;
    const int gstride = NBLK * NTHR;
    for (int idx = gid; idx < 150 * 152; idx += gstride) {
        int h = idx / 152, d = idx - h * 152;
        d_WpE[idx] = (d < 150) ? Wp[h * 300 + d] + Wp[h * 300 + 150 + d] : 0.f;
        d_WqE[idx] = (d < 150) ? Wq[h * 300 + d] + Wq[h * 300 + 150 + d] : 0.f;
    }
    for (int idx = gid; idx < 600 * 152; idx += gstride) {
        int j = idx / 152, k = idx - j * 152;
        d_WgU[idx] = (k < 150) ? Wg[j * 600 + k] + Wg[j * 600 + 150 + k] : 0.f;
    }
    for (int idx = gid; idx < WV_NCH * WV_NJT * 32; idx += gstride) {
        int lane = idx & 31, rest = idx >> 5;
        int jt = rest % WV_NJT, kc = rest / WV_NJT;
        int m = lane & 3, j = 8 * jt + (lane >> 2);
        int k0 = kc * 16 + 2 * m;
        float v00 = 0.f, v01 = 0.f, v10 = 0.f, v11 = 0.f;
        if (j < 150) {
            if (k0     < 150) v00 = Wv[j * 150 + k0];
            if (k0 + 1 < 150) v01 = Wv[j * 150 + k0 + 1];
            if (k0 + 8 < 150) v10 = Wv[j * 150 + k0 + 8];
            if (k0 + 9 < 150) v11 = Wv[j * 150 + k0 + 9];
        }
        g_WvPk[idx] = make_uint2(pack2(v00, v01), pack2(v10, v11));
    }
    for (int idx = gid; idx < WHH_NCH * WHH_NJT * 32; idx += gstride) {
        int lane = idx & 31, rest = idx >> 5;
        int jt = rest % WHH_NJT, kc = rest / WHH_NJT;
        int m = lane & 3, j = 8 * jt + (lane >> 2);
        int k0 = kc * 16 + 2 * m;
        float v00 = 0.f, v01 = 0.f, v10 = 0.f, v11 = 0.f;
        if (j < 450) {
            if (k0     < 150) v00 = W_hh[j * 150 + k0];
            if (k0 + 1 < 150) v01 = W_hh[j * 150 + k0 + 1];
            if (k0 + 8 < 150) v10 = W_hh[j * 150 + k0 + 8];
            if (k0 + 9 < 150) v11 = W_hh[j * 150 + k0 + 9];
        }
        g_WhhPk[idx] = make_uint2(pack2(v00, v01), pack2(v10, v11));
    }
    for (int idx = gid; idx < WGC_NCH * WGC_NJT * 32; idx += gstride) {
        int lane = idx & 31, rest = idx >> 5;
        int jt = rest % WGC_NJT, kc = rest / WGC_NJT;
        int m = lane & 3, j = 8 * jt + (lane >> 2);
        int k0 = kc * 16 + 2 * m;
        float v00 = 0.f, v01 = 0.f, v10 = 0.f, v11 = 0.f;
        if (k0     < 150) v00 = Wg[j * 600 + 300 + k0]     + Wg[j * 600 + 450 + k0];
        if (k0 + 1 < 150) v01 = Wg[j * 600 + 300 + k0 + 1] + Wg[j * 600 + 450 + k0 + 1];
        if (k0 + 8 < 150) v10 = Wg[j * 600 + 300 + k0 + 8] + Wg[j * 600 + 450 + k0 + 8];
        if (k0 + 9 < 150) v11 = Wg[j * 600 + 300 + k0 + 9] + Wg[j * 600 + 450 + k0 + 9];
        g_WgCPk[idx] = make_uint2(pack2(v00, v01), pack2(v10, v11));
    }
    for (int idx = gid; idx < WIH_NCH * WIH_NJT * 32; idx += gstride) {
        int lane = idx & 31, rest = idx >> 5;
        int jt = rest % WIH_NJT, kc = rest / WIH_NJT;
        int m = lane & 3, j = 8 * jt + (lane >> 2);
        int k0 = kc * 16 + 2 * m;
        float v00 = 0.f, v01 = 0.f, v10 = 0.f, v11 = 0.f;
        if (j < 450) {
            if (k0     < 600) v00 = W_ih[j * 600 + k0];
            if (k0 + 1 < 600) v01 = W_ih[j * 600 + k0 + 1];
            if (k0 + 8 < 600) v10 = W_ih[j * 600 + k0 + 8];
            if (k0 + 9 < 600) v11 = W_ih[j * 600 + k0 + 9];
        }
        g_WihPk[idx] = make_uint2(pack2(v00, v01), pack2(v10, v11));
    }
    gsync(gen);   // the ONLY grid barrier

    // ======== P1 (block-local): per-batch precompute for BOTH batches ========
    // Phase 1: gu/wup from fp32 Up staged in the (not-yet-used) WUQH region
    {
        float* A = sm + WUQH_S;   // 19456 fp32 slots <= 19712
        for (int bb = 0; bb < 2; bb++) {
            const int b = 2 * blk + bb;
            for (int t = tid; t < 128 * 150; t += NTHR) {
                int ii = t / 150, k = t - ii * 150;
                A[ii * 152 + k] = Up[(ii * Bn + b) * 150 + k];
            }
            __syncthreads();
            for (int task = tid; task < 16 * 600; task += NTHR) {
                int j = task % 600, it = task / 600;
                float acc[8] = {0.f, 0.f, 0.f, 0.f, 0.f, 0.f, 0.f, 0.f};
                const float4* wr = (const float4*)(d_WgU + j * 152);
                for (int q = 0; q < 38; q++) {
                    float4 w4 = wr[q];
#pragma unroll
                    for (int ii = 0; ii < 8; ii++) {
                        const float* xr = A + (it * 8 + ii) * 152 + q * 4;
                        acc[ii] += w4.x * xr[0] + w4.y * xr[1] + w4.z * xr[2] + w4.w * xr[3];
                    }
                }
#pragma unroll
                for (int ii = 0; ii < 8; ii++)
                    d_gu[(b * LPn + it * 8 + ii) * 600 + j] = acc[ii];
            }
            for (int task = tid; task < 16 * 150; task += NTHR) {
                int h = task % 150, it = task / 150;
                float acc[8] = {0.f, 0.f, 0.f, 0.f, 0.f, 0.f, 0.f, 0.f};
                const float4* wr = (const float4*)(d_WpE + h * 152);
                for (int q = 0; q < 38; q++) {
                    float4 w4 = wr[q];
#pragma unroll
                    for (int ii = 0; ii < 8; ii++) {
                        const float* xr = A + (it * 8 + ii) * 152 + q * 4;
                        acc[ii] += w4.x * xr[0] + w4.y * xr[1] + w4.z * xr[2] + w4.w * xr[3];
                    }
                }
#pragma unroll
                for (int ii = 0; ii < 8; ii++)
                    d_wup[(b * LPn + it * 8 + ii) * 150 + h] = acc[ii];
            }
            __syncthreads();
        }
    }
    // Phase 2: Uq fp16 -> UQH[bb]; Wuq (fp16 x) -> WUQH[bb]
    for (int bb = 0; bb < 2; bb++) {
        const int b = 2 * blk + bb;
        __half* uqh = UQH + bb * 19456;
        for (int t = tid; t < 128 * 150; t += NTHR) {
            int l = t / 150, d = t - l * 150;
            uqh[l * 152 + d] = __float2half_rn(Uq[(l * Bn + b) * 150 + d]);
        }
        __syncthreads();
        for (int task = tid; task < 16 * 150; task += NTHR) {
            int h = task % 150, lt = task / 150;
            float acc[8] = {0.f, 0.f, 0.f, 0.f, 0.f, 0.f, 0.f, 0.f};
            const float4* wr = (const float4*)(d_WqE + h * 152);
            for (int q = 0; q < 38; q++) {
                float4 w4 = wr[q];
#pragma unroll
                for (int ii = 0; ii < 8; ii++) {
                    const __half2* xr = (const __half2*)(uqh + (lt * 8 + ii) * 152);
                    float2 xa = __half22float2(xr[2 * q]);
                    float2 xb = __half22float2(xr[2 * q + 1]);
                    acc[ii] += w4.x * xa.x + w4.y * xa.y + w4.z * xb.x + w4.w * xb.y;
                }
            }
#pragma unroll
            for (int ii = 0; ii < 8; ii++)
                WUQH[bb * 19712 + (lt * 8 + ii) * 154 + h] = __float2half_rn(acc[ii]);
        }
        __syncthreads();
    }
    // init per-batch state
    if (tid < 300) {
        int bb = tid / 150, h = tid - bb * 150;
        float* scrB = sm + SCR + bb * SCB;
        scrB[R_V + h]  = v0[(2 * blk + bb) * 150 + h];
        scrB[R_VB + h] = Vmat[(2 * blk + bb) * 150 + h];
    }
    __syncthreads();
    if (tid < 160) {
        int bb = tid / 80, p = tid - bb * 80;
        float* scrB = sm + SCR + bb * SCB;
        float x0 = (2 * p     < 150) ? scrB[R_V + 2 * p]     : 0.f;
        float x1 = (2 * p + 1 < 150) ? scrB[R_V + 2 * p + 1] : 0.f;
        ((unsigned*)(scrB + R_VP))[p] = pack2(x0, x1);
    }
    if (tid >= 256 && tid < 266) {
        int bb = (tid - 256) / 5, p = 75 + (tid - 256) % 5;
        ((unsigned*)(sm + SCR + bb * SCB + R_CP2))[p] = 0u;
    }
    if (tid >= 512 && tid < 552) {
        int bb = (tid - 512) / 20, p = 300 + (tid - 512) % 20;
        ((unsigned*)(sm + SCR + bb * SCB + R_RGP))[p] = 0u;
    }
    __syncthreads();

    float* scr0 = sm + SCR;
    float* scr1 = sm + SCR + SCB;
    const int hb = tid >> 9;            // scalar-half: 0 -> batch0, 1 -> batch1
    const int th = tid & 511;
    float* scrH = sm + SCR + hb * SCB;  // this scalar-half's scratch

    // ======== main scan: 128 steps, block-local ========
    for (int i = 0; i < LPn; i++) {
        // ---- Stage A: wv (w0-7, dual) | gh (w8-23, dual) | staging (w24-31) ----
        if (w < 8) {
            int kg = w >> 2, jgl = w & 3;
            float d[5][4];
#pragma unroll
            for (int t = 0; t < 5; t++) { d[t][0]=d[t][1]=d[t][2]=d[t][3]=0.f; }
            gemv2<5>(d, g_WvPk, WV_NJT, kg * 5, kg * 5 + 5, jgl * 5,
                     (unsigned*)(scr0 + R_VP), (unsigned*)(scr1 + R_VP), ln);
            store2<5>(d, scr0 + R_WVP + kg * 160, scr1 + R_WVP + kg * 160, jgl * 5, ln);
        } else if (w < 24) {
            int wl = w - 8;
            if (wl < 10) {
                int jt0 = wl * 4;
                float d[4][4];
#pragma unroll
                for (int t = 0; t < 4; t++) { d[t][0]=d[t][1]=d[t][2]=d[t][3]=0.f; }
                gemv2<4>(d, g_WhhPk, WHH_NJT, 0, 10, jt0,
                         (unsigned*)(scr0 + R_VP), (unsigned*)(scr1 + R_VP), ln);
                store2_gh<4>(d, scr0 + R_GH, scr1 + R_GH, jt0, ln, b_hh);
            } else {
                int jt0 = 40 + (wl - 10) * 3;
                float d[3][4];
#pragma unroll
                for (int t = 0; t < 3; t++) { d[t][0]=d[t][1]=d[t][2]=d[t][3]=0.f; }
                gemv2<3>(d, g_WhhPk, WHH_NJT, 0, 10, jt0,
                         (unsigned*)(scr0 + R_VP), (unsigned*)(scr1 + R_VP), ln);
                store2_gh<3>(d, scr0 + R_GH, scr1 + R_GH, jt0, ln, b_hh);
            }
        } else {
            for (int t = tid - 768; t < 1800; t += 256) {
                int bb = t / 900, r = t - bb * 900;
                int b = 2 * blk + bb;
                float* scrB = sm + SCR + bb * SCB;
                if (r < 150)      scrB[R_U + r]         = Up[(i * Bn + b) * 150 + r];
                else if (r < 300) scrB[R_BSE + r - 150] = d_wup[(b * LPn + i) * 150 + r - 150];
                else              scrB[R_GU + r - 300]  = d_gu[(b * LPn + i) * 600 + r - 300];
            }
        }
        __syncthreads();
        // ---- bse combine ----
        if (tid < 300) {
            int bb = tid / 150, h = tid - bb * 150;
            float* scrB = sm + SCR + bb * SCB;
            scrB[R_BSE + h] += scrB[R_WVP + h] + scrB[R_WVP + 160 + h];
        }
        __syncthreads();
        // ---- S3: s[l] partials; each 512-half owns one batch (128 l x 4 kg) ----
        {
            int l = th & 127, g = th >> 7;        // g in 0..3
            int p0 = (g * 75) >> 2, p1 = ((g + 1) * 75) >> 2;
            const __half2* wq2 = (const __half2*)(WUQH + hb * 19712 + l * 154);
            const float2* bse2 = (const float2*)(scrH + R_BSE);
            const float2* vb2  = (const float2*)(scrH + R_VB);
            float acc = 0.f;
#pragma unroll 5
            for (int p = p0; p < p1; p++) {
                float2 wq = __half22float2(wq2[p]);
                float2 bs = bse2[p], vb = vb2[p];
                acc += tanh_fastest(bs.x + wq.x) * vb.x
                     + tanh_fastest(bs.y + wq.y) * vb.y;
            }
            scrH[R_AP + g * 128 + l] = acc;
        }
        __syncthreads();
        // ---- softmax: warp 0 -> batch0, warp 16 -> batch1 ----
        if ((w & 15) == 0) {
            int bb = w >> 4;
            float* scrB = sm + SCR + bb * SCB;
            float a0 = 0.f, a1 = 0.f, a2 = 0.f, a3 = 0.f;
#pragma unroll
            for (int g = 0; g < 4; g++) {
                const float* apg = scrB + R_AP + g * 128;
                a0 += apg[ln]; a1 += apg[32 + ln]; a2 += apg[64 + ln]; a3 += apg[96 + ln];
            }
            float m = fmaxf(fmaxf(a0, a1), fmaxf(a2, a3));
            m = warp_max_all(m);
            float e0 = __expf(a0 - m), e1 = __expf(a1 - m);
            float e2 = __expf(a2 - m), e3 = __expf(a3 - m);
            float ssum = warp_sum_all(e0 + e1 + e2 + e3);
            float inv = __fdividef(1.0f, ssum);
            scrB[R_A + ln] = e0 * inv; scrB[R_A + 32 + ln] = e1 * inv;
            scrB[R_A + 64 + ln] = e2 * inv; scrB[R_A + 96 + ln] = e3 * inv;
        }
        __syncthreads();
        // ---- cc partials: per half, 4 l-groups x 150 d over its batch ----
        for (int t = th; t < 600; t += 512) {
            int lq = t / 150, d = t - lq * 150;
            const __half* uq = UQH + hb * 19456 + lq * 32 * 152 + d;
            const float* av = scrH + R_A + lq * 32;
            float acc = 0.f;
#pragma unroll
            for (int q = 0; q < 32; q++) acc += av[q] * __half2float(uq[q * 152]);
            scrH[R_CCP + lq * 152 + d] = acc;
        }
        __syncthreads();
        // ---- cc combine + pairs (150 thr: 2 batches x 75 pair-tasks) ----
        if (tid < 150) {
            int bb = tid / 75, tp = tid - bb * 75;
            float* scrB = sm + SCR + bb * SCB;
            int d0 = 2 * tp, d1 = d0 + 1;
            float c0 = 0.f, c1 = 0.f;
#pragma unroll
            for (int g = 0; g < 4; g++) {
                c0 += scrB[R_CCP + g * 152 + d0];
                c1 += scrB[R_CCP + g * 152 + d1];
            }
            scrB[R_CC + d0] = c0; scrB[R_CC + d1] = c1;
            ((unsigned*)(scrB + R_CP2))[tp] = pack2(c0, c1);
        }
        __syncthreads();
        // ---- B mma (w0-29, dual): bp = cc @ WgC^T partials ----
        if (w < 30) {
            int kg = w / 15, jgl = w - kg * 15;
            float d[5][4];
#pragma unroll
            for (int t = 0; t < 5; t++) { d[t][0]=d[t][1]=d[t][2]=d[t][3]=0.f; }
            gemv2<5>(d, g_WgCPk, WGC_NJT, kg * 5, kg * 5 + 5, jgl * 5,
                     (unsigned*)(scr0 + R_CP2), (unsigned*)(scr1 + R_CP2), ln);
            store2<5>(d, scr0 + R_BP + kg * 600, scr1 + R_BP + kg * 600, jgl * 5, ln);
        }
        __syncthreads();
        // ---- B combine (600 thr: bb x 300 j-pairs): rg pairs ----
        if (tid < 600) {
            int bb = tid / 300, jp = tid - bb * 300;
            float* scrB = sm + SCR + bb * SCB;
            float r2[2];
#pragma unroll
            for (int s = 0; s < 2; s++) {
                int j = 2 * jp + s;
                float g = scrB[R_GU + j] + scrB[R_BP + j] + scrB[R_BP + 600 + j];
                float sg = fast_sig(g);
                int km = (j < 150) ? j : (j < 300) ? j - 150 : (j < 450) ? j - 300 : j - 450;
                float rb = (j < 300) ? scrB[R_U + km] : scrB[R_CC + km];
                r2[s] = sg * rb;
            }
            ((unsigned*)(scrB + R_RGP))[jp] = pack2(r2[0], r2[1]);
        }
        __syncthreads();
        // ---- C mma (all 32, dual): cp = rg @ W_ih^T partials ----
        {
            int kg = w >> 4, jgl = w & 15;
            if (jgl < 10) {
                int jt0 = jgl * 4;
                float d[4][4];
#pragma unroll
                for (int t = 0; t < 4; t++) { d[t][0]=d[t][1]=d[t][2]=d[t][3]=0.f; }
                gemv2<4>(d, g_WihPk, WIH_NJT, kg * 20, kg * 20 + 20, jt0,
                         (unsigned*)(scr0 + R_RGP), (unsigned*)(scr1 + R_RGP), ln);
                store2<4>(d, scr0 + R_CPP + kg * 464, scr1 + R_CPP + kg * 464, jt0, ln);
            } else {
                int jt0 = 40 + (jgl - 10) * 3;
                float d[3][4];
#pragma unroll
                for (int t = 0; t < 3; t++) { d[t][0]=d[t][1]=d[t][2]=d[t][3]=0.f; }
                gemv2<3>(d, g_WihPk, WIH_NJT, kg * 20, kg * 20 + 20, jt0,
                         (unsigned*)(scr0 + R_RGP), (unsigned*)(scr1 + R_RGP), ln);
                store2<3>(d, scr0 + R_CPP + kg * 464, scr1 + R_CPP + kg * 464, jt0, ln);
            }
        }
        __syncthreads();
        // ---- GRU combine (150 thr: bb x 75 pair-tasks) + v pairs ----
        if (tid < 150) {
            int bb = tid / 75, tp = tid - bb * 75;
            int b = 2 * blk + bb;
            float* scrB = sm + SCR + bb * SCB;
            float hn2[2];
#pragma unroll
            for (int s = 0; s < 2; s++) {
                int h = 2 * tp + s;
                float ir  = b_ih[h]       + scrB[R_CPP + h]       + scrB[R_CPP + 464 + h];
                float iz  = b_ih[150 + h] + scrB[R_CPP + 150 + h] + scrB[R_CPP + 614 + h];
                float in_ = b_ih[300 + h] + scrB[R_CPP + 300 + h] + scrB[R_CPP + 764 + h];
                float r_ = fast_sig(ir + scrB[R_GH + h]);
                float z_ = fast_sig(iz + scrB[R_GH + 150 + h]);
                float n_ = fast_tanh(in_ + r_ * scrB[R_GH + 300 + h]);
                float hnew = (1.0f - z_) * n_ + z_ * scrB[R_V + h];
                out[(i * Bn + b) * 150 + h] = hnew;
                scrB[R_V + h] = hnew;
                hn2[s] = hnew;
            }
            ((unsigned*)(scrB + R_VP))[tp] = pack2(hn2[0], hn2[1]);
        }
        __syncthreads();
    }
}

// ---------------- launch ----------------
extern "C" void kernel_launch(void* const* d_in, const int* in_sizes, int n_in,
                              void* d_out, int out_size)
{
    const float* Up   = (const float*)d_in[0];
    const float* Uq   = (const float*)d_in[1];
    const float* Wp   = (const float*)d_in[2];
    const float* Wq   = (const float*)d_in[3];
    const float* Wv   = (const float*)d_in[4];
    const float* Wg   = (const float*)d_in[5];
    const float* Vm   = (const float*)d_in[6];
    const float* v0   = (const float*)d_in[7];
    const float* W_ih = (const float*)d_in[8];
    const float* W_hh = (const float*)d_in[9];
    const float* b_ih = (const float*)d_in[10];
    const float* b_hh = (const float*)d_in[11];
    float* out = (float*)d_out;

    cudaFuncSetAttribute(pqm_kernel, cudaFuncAttributeMaxDynamicSharedMemorySize, SMEM_BYTES);
    pqm_kernel<<<NBLK, NTHR, SMEM_BYTES>>>(Up, Uq, Wp, Wq, Wv, Wg, Vm, v0,
                                           W_ih, W_hh, b_ih, b_hh, out);
}

// round 13
// speedup vs baseline: 1.2692x; 1.2692x over previous
#include <cuda_runtime.h>
#include <cuda_fp16.h>

// ---------------- problem constants ----------------
#define NBLK 64
#define NTHR 1024
#define LPn  128
#define Bn   64

// packed-weight tile grids (16k x 8j tiles, B-fragment order)
#define WV_NCH  10
#define WV_NJT  20
#define WHH_NCH 10
#define WHH_NJT 60     // padded (450 j -> 57 tiles, pad to 60 for 12jg x NT5)
#define WGC_NCH 10
#define WGC_NJT 75
#define WIH_NCH 40
#define WIH_NJT 64     // padded (450 j -> 57 tiles, pad to 64 for 8jg x NT8)

// ---------------- device scratch ----------------
__device__ float d_WpE[150 * 152];
__device__ float d_WqE[150 * 152];
__device__ float d_WgU[600 * 152];
__device__ uint2 g_WvPk [WV_NCH  * WV_NJT  * 32];   // Wv^T    (k x j=150)
__device__ uint2 g_WhhPk[WHH_NCH * WHH_NJT * 32];   // W_hh^T  (k x j=450, pad)
__device__ uint2 g_WgCPk[WGC_NCH * WGC_NJT * 32];   // WgC^T   (k x j=600)
__device__ uint2 g_WihPk[WIH_NCH * WIH_NJT * 32];   // W_ih^T  (k=600 x j=450, pad)
__device__ float d_wup[Bn * LPn * 150];
__device__ float d_gu [Bn * LPn * 600];
__device__ unsigned g_flags[NBLK];
__device__ unsigned g_rel2;

// ---------------- smem layout (float slots) ----------------
#define WUQ_S  0                      // Wuq fp32 [l*153+h] (128x153=19584); P1: Up staging
#define UQH_S  19584                  // Uq fp16 [l*152+d] = 9728 float slots
#define SCR    29312
#define V_S    (SCR + 0)              // 152
#define VB_S   (SCR + 152)            // 152
#define U_S    (SCR + 304)            // 152
#define BSE_S  (SCR + 456)            // 152
#define CC_S   (SCR + 608)            // 152
#define A_S    (SCR + 760)            // 128
#define GU_S   (SCR + 888)            // 600
#define GH_S   (SCR + 1488)           // 464
#define VP_S   (SCR + 1952)           // 80  uint pairs of v (k pad 160)
#define CP2_S  (SCR + 2032)           // 80  uint pairs of cc
#define RGP_S  (SCR + 2112)           // 320 uint pairs of rg (k pad 640)
#define WVP_S  (SCR + 2432)           // 2 x 160 wv partials
#define BP_S   (SCR + 2752)           // 2 x 600 B partials
#define CPP_S  (SCR + 3952)           // 4 x 512 C partials
#define CCP_S  (SCR + 6000)           // 8 x 152 cc partials
#define GHP_S  (SCR + 7216)           // 2 x 480 gh partials
#define AP_S   (SCR + 8176)           // 1024 s partials
#define SMEM_FL (SCR + 9200)          // 38512 floats
#define SMEM_BYTES (SMEM_FL * 4)      // 154048 B

// ---------------- helpers ----------------
__device__ __forceinline__ float warp_max_all(float v) {
#pragma unroll
    for (int o = 16; o > 0; o >>= 1) v = fmaxf(v, __shfl_xor_sync(0xffffffffu, v, o));
    return v;
}
__device__ __forceinline__ float warp_sum_all(float v) {
#pragma unroll
    for (int o = 16; o > 0; o >>= 1) v += __shfl_xor_sync(0xffffffffu, v, o);
    return v;
}
__device__ __forceinline__ float fast_sig(float x) {
    return 1.0f / (1.0f + __expf(-x));
}
__device__ __forceinline__ float fast_tanh(float x) {
    float cx = fminf(fmaxf(x, -15.0f), 15.0f);
    float e  = __expf(2.0f * cx);
    return __fdividef(e - 1.0f, e + 1.0f);
}
__device__ __forceinline__ float tanh_fastest(float x) {
    float y;
    asm("tanh.approx.f32 %0, %1;" : "=f"(y) : "f"(x));
    return y;
}
__device__ __forceinline__ unsigned pack2(float x, float y) {
    __half2 h = __floats2half2_rn(x, y);
    return *reinterpret_cast<unsigned*>(&h);
}

// m16n8k16 f16 MMA, f32 accumulate. A rows 1-15 zero (GEMV): a-regs {xlow, 0, xhigh, 0}.
__device__ __forceinline__ void mma16816(float* d, unsigned a0, unsigned a1,
                                         unsigned b0, unsigned b1) {
    asm volatile(
        "mma.sync.aligned.m16n8k16.row.col.f32.f16.f16.f32 "
        "{%0,%1,%2,%3}, {%4,%5,%6,%7}, {%8,%9}, {%0,%1,%2,%3};"
        : "+f"(d[0]), "+f"(d[1]), "+f"(d[2]), "+f"(d[3])
        : "r"(a0), "r"(0u), "r"(a1), "r"(0u), "r"(b0), "r"(b1));
}

// GEMV tile loop: accumulate NT j-tiles over chunks [kc0,kc1). (NT <= 5)
template<int NT>
__device__ __forceinline__ void gemv_acc(float d[][4], const uint2* __restrict__ Wpk,
                                         int njt, int kc0, int kc1, int jt0,
                                         const unsigned* __restrict__ xp, int ln) {
    for (int kc = kc0; kc < kc1; kc++) {
        unsigned a0 = 0, a1 = 0;
        if (ln < 4) { a0 = xp[kc * 8 + ln]; a1 = xp[kc * 8 + 4 + ln]; }
        const uint2* wr = Wpk + (kc * njt + jt0) * 32 + ln;
#pragma unroll
        for (int t = 0; t < NT; t++) {
            uint2 bb = __ldg(&wr[t * 32]);
            mma16816(d[t], a0, a1, bb.x, bb.y);
        }
    }
}
// 8-tile variant with 4+4 load batching (caps live buffers; fits 64 regs)
__device__ __forceinline__ void gemv_acc8(float d[][4], const uint2* __restrict__ Wpk,
                                          int njt, int kc0, int kc1, int jt0,
                                          const unsigned* __restrict__ xp, int ln) {
    for (int kc = kc0; kc < kc1; kc++) {
        unsigned a0 = 0, a1 = 0;
        if (ln < 4) { a0 = xp[kc * 8 + ln]; a1 = xp[kc * 8 + 4 + ln]; }
        const uint2* wr = Wpk + (kc * njt + jt0) * 32 + ln;
        uint2 b0 = __ldg(&wr[0]),  b1 = __ldg(&wr[32]);
        uint2 b2 = __ldg(&wr[64]), b3 = __ldg(&wr[96]);
        mma16816(d[0], a0, a1, b0.x, b0.y);
        mma16816(d[1], a0, a1, b1.x, b1.y);
        mma16816(d[2], a0, a1, b2.x, b2.y);
        mma16816(d[3], a0, a1, b3.x, b3.y);
        uint2 b4 = __ldg(&wr[128]), b5 = __ldg(&wr[160]);
        uint2 b6 = __ldg(&wr[192]), b7 = __ldg(&wr[224]);
        mma16816(d[4], a0, a1, b4.x, b4.y);
        mma16816(d[5], a0, a1, b5.x, b5.y);
        mma16816(d[6], a0, a1, b6.x, b6.y);
        mma16816(d[7], a0, a1, b7.x, b7.y);
    }
}
template<int NT>
__device__ __forceinline__ void store_part(const float d[][4], float* dst,
                                           int jt0, int ln) {
    if (ln < 4) {
#pragma unroll
        for (int t = 0; t < NT; t++)
            *(float2*)(dst + (jt0 + t) * 8 + 2 * ln) = make_float2(d[t][0], d[t][1]);
    }
}

// Flag-array grid barrier (prologue only). Monotonic, atomic-free.
__device__ __forceinline__ void gsync(unsigned& gen) {
    __syncthreads();
    const unsigned target = gen + 1u;
    if (blockIdx.x == 0) {
        if (threadIdx.x < 32) {
            const int ln = threadIdx.x;
            if (ln == 0) *((volatile unsigned*)&g_flags[0]) = target;
            bool ok;
            do {
                unsigned f0, f1;
                asm volatile("ld.acquire.gpu.u32 %0, [%1];" : "=r"(f0) : "l"(&g_flags[ln]));
                asm volatile("ld.acquire.gpu.u32 %0, [%1];" : "=r"(f1) : "l"(&g_flags[ln + 32]));
                ok = (f0 >= target) & (f1 >= target);
            } while (!__all_sync(0xffffffffu, ok));
            if (ln == 0)
                asm volatile("st.release.gpu.u32 [%0], %1;" :: "l"(&g_rel2), "r"(target) : "memory");
        }
    } else {
        if (threadIdx.x == 0) {
            asm volatile("st.release.gpu.u32 [%0], %1;"
                         :: "l"(&g_flags[blockIdx.x]), "r"(target) : "memory");
            unsigned r;
            do {
                asm volatile("ld.acquire.gpu.u32 %0, [%1];" : "=r"(r) : "l"(&g_rel2));
            } while (r < target);
        }
    }
    gen = target;
    __syncthreads();
}

// ---------------- the persistent kernel: one block per batch ----------------
__global__ void __launch_bounds__(NTHR, 1) pqm_kernel(
    const float* __restrict__ Up, const float* __restrict__ Uq,
    const float* __restrict__ Wp, const float* __restrict__ Wq,
    const float* __restrict__ Wv, const float* __restrict__ Wg,
    const float* __restrict__ Vmat, const float* __restrict__ v0,
    const float* __restrict__ W_ih, const float* __restrict__ W_hh,
    const float* __restrict__ b_ih, const float* __restrict__ b_hh,
    float* __restrict__ out)
{
    extern __shared__ float sm[];
    __half* UQH = (__half*)(sm + UQH_S);
    unsigned* vpair  = (unsigned*)(sm + VP_S);
    unsigned* ccpair = (unsigned*)(sm + CP2_S);
    unsigned* rgpair = (unsigned*)(sm + RGP_S);
    const int tid = threadIdx.x;
    const int b   = blockIdx.x;
    const int w   = tid >> 5, ln = tid & 31;

    unsigned gen = *((volatile unsigned*)&g_rel2);

    // ======== P0: folds + packed fp16 B-fragment weight builds ========
    const int gid = b * NTHR + tid;
    const int gstride = NBLK * NTHR;
    for (int idx = gid; idx < 150 * 152; idx += gstride) {
        int h = idx / 152, d = idx - h * 152;
        d_WpE[idx] = (d < 150) ? Wp[h * 300 + d] + Wp[h * 300 + 150 + d] : 0.f;
        d_WqE[idx] = (d < 150) ? Wq[h * 300 + d] + Wq[h * 300 + 150 + d] : 0.f;
    }
    for (int idx = gid; idx < 600 * 152; idx += gstride) {
        int j = idx / 152, k = idx - j * 152;
        d_WgU[idx] = (k < 150) ? Wg[j * 600 + k] + Wg[j * 600 + 150 + k] : 0.f;
    }
    for (int idx = gid; idx < WV_NCH * WV_NJT * 32; idx += gstride) {
        int lane = idx & 31, rest = idx >> 5;
        int jt = rest % WV_NJT, kc = rest / WV_NJT;
        int m = lane & 3, j = 8 * jt + (lane >> 2);
        int k0 = kc * 16 + 2 * m;
        float v00 = 0.f, v01 = 0.f, v10 = 0.f, v11 = 0.f;
        if (j < 150) {
            if (k0     < 150) v00 = Wv[j * 150 + k0];
            if (k0 + 1 < 150) v01 = Wv[j * 150 + k0 + 1];
            if (k0 + 8 < 150) v10 = Wv[j * 150 + k0 + 8];
            if (k0 + 9 < 150) v11 = Wv[j * 150 + k0 + 9];
        }
        g_WvPk[idx] = make_uint2(pack2(v00, v01), pack2(v10, v11));
    }
    for (int idx = gid; idx < WHH_NCH * WHH_NJT * 32; idx += gstride) {
        int lane = idx & 31, rest = idx >> 5;
        int jt = rest % WHH_NJT, kc = rest / WHH_NJT;
        int m = lane & 3, j = 8 * jt + (lane >> 2);
        int k0 = kc * 16 + 2 * m;
        float v00 = 0.f, v01 = 0.f, v10 = 0.f, v11 = 0.f;
        if (j < 450) {
            if (k0     < 150) v00 = W_hh[j * 150 + k0];
            if (k0 + 1 < 150) v01 = W_hh[j * 150 + k0 + 1];
            if (k0 + 8 < 150) v10 = W_hh[j * 150 + k0 + 8];
            if (k0 + 9 < 150) v11 = W_hh[j * 150 + k0 + 9];
        }
        g_WhhPk[idx] = make_uint2(pack2(v00, v01), pack2(v10, v11));
    }
    for (int idx = gid; idx < WGC_NCH * WGC_NJT * 32; idx += gstride) {
        int lane = idx & 31, rest = idx >> 5;
        int jt = rest % WGC_NJT, kc = rest / WGC_NJT;
        int m = lane & 3, j = 8 * jt + (lane >> 2);
        int k0 = kc * 16 + 2 * m;
        float v00 = 0.f, v01 = 0.f, v10 = 0.f, v11 = 0.f;
        if (k0     < 150) v00 = Wg[j * 600 + 300 + k0]     + Wg[j * 600 + 450 + k0];
        if (k0 + 1 < 150) v01 = Wg[j * 600 + 300 + k0 + 1] + Wg[j * 600 + 450 + k0 + 1];
        if (k0 + 8 < 150) v10 = Wg[j * 600 + 300 + k0 + 8] + Wg[j * 600 + 450 + k0 + 8];
        if (k0 + 9 < 150) v11 = Wg[j * 600 + 300 + k0 + 9] + Wg[j * 600 + 450 + k0 + 9];
        g_WgCPk[idx] = make_uint2(pack2(v00, v01), pack2(v10, v11));
    }
    for (int idx = gid; idx < WIH_NCH * WIH_NJT * 32; idx += gstride) {
        int lane = idx & 31, rest = idx >> 5;
        int jt = rest % WIH_NJT, kc = rest / WIH_NJT;
        int m = lane & 3, j = 8 * jt + (lane >> 2);
        int k0 = kc * 16 + 2 * m;
        float v00 = 0.f, v01 = 0.f, v10 = 0.f, v11 = 0.f;
        if (j < 450) {
            if (k0     < 600) v00 = W_ih[j * 600 + k0];
            if (k0 + 1 < 600) v01 = W_ih[j * 600 + k0 + 1];
            if (k0 + 8 < 600) v10 = W_ih[j * 600 + k0 + 8];
            if (k0 + 9 < 600) v11 = W_ih[j * 600 + k0 + 9];
        }
        g_WihPk[idx] = make_uint2(pack2(v00, v01), pack2(v10, v11));
    }
    gsync(gen);   // the ONLY grid barrier

    // ======== P1 (block-local): per-batch precompute ========
    {
        float* A = sm + WUQ_S;     // Up staging [i*152+k] (19456 <= 19584)
        for (int t = tid; t < 128 * 150; t += NTHR) {
            int ii = t / 150, k = t - ii * 150;
            A[ii * 152 + k] = Up[(ii * Bn + b) * 150 + k];
        }
        __syncthreads();
        for (int task = tid; task < 16 * 600; task += NTHR) {
            int j = task % 600, it = task / 600;
            float acc[8] = {0.f, 0.f, 0.f, 0.f, 0.f, 0.f, 0.f, 0.f};
            const float4* wr = (const float4*)(d_WgU + j * 152);
            for (int q = 0; q < 38; q++) {
                float4 w4 = wr[q];
#pragma unroll
                for (int ii = 0; ii < 8; ii++) {
                    const float* xr = A + (it * 8 + ii) * 152 + q * 4;
                    acc[ii] += w4.x * xr[0] + w4.y * xr[1] + w4.z * xr[2] + w4.w * xr[3];
                }
            }
#pragma unroll
            for (int ii = 0; ii < 8; ii++)
                d_gu[(b * LPn + it * 8 + ii) * 600 + j] = acc[ii];
        }
        for (int task = tid; task < 16 * 150; task += NTHR) {
            int h = task % 150, it = task / 150;
            float acc[8] = {0.f, 0.f, 0.f, 0.f, 0.f, 0.f, 0.f, 0.f};
            const float4* wr = (const float4*)(d_WpE + h * 152);
            for (int q = 0; q < 38; q++) {
                float4 w4 = wr[q];
#pragma unroll
                for (int ii = 0; ii < 8; ii++) {
                    const float* xr = A + (it * 8 + ii) * 152 + q * 4;
                    acc[ii] += w4.x * xr[0] + w4.y * xr[1] + w4.z * xr[2] + w4.w * xr[3];
                }
            }
#pragma unroll
            for (int ii = 0; ii < 8; ii++)
                d_wup[(b * LPn + it * 8 + ii) * 150 + h] = acc[ii];
        }
        __syncthreads();
        // Uq fp16 -> UQH; Wuq (fp32 accum, fp16 x) -> WUQ_S (stride 153)
        for (int t = tid; t < 128 * 150; t += NTHR) {
            int l = t / 150, d = t - l * 150;
            UQH[l * 152 + d] = __float2half_rn(Uq[(l * Bn + b) * 150 + d]);
        }
        __syncthreads();
        for (int task = tid; task < 16 * 150; task += NTHR) {
            int h = task % 150, lt = task / 150;
            float acc[8] = {0.f, 0.f, 0.f, 0.f, 0.f, 0.f, 0.f, 0.f};
            const float4* wr = (const float4*)(d_WqE + h * 152);
            for (int q = 0; q < 38; q++) {
                float4 w4 = wr[q];
#pragma unroll
                for (int ii = 0; ii < 8; ii++) {
                    const __half2* xr = (const __half2*)(UQH + (lt * 8 + ii) * 152);
                    float2 xa = __half22float2(xr[2 * q]);
                    float2 xb = __half22float2(xr[2 * q + 1]);
                    acc[ii] += w4.x * xa.x + w4.y * xa.y + w4.z * xb.x + w4.w * xb.y;
                }
            }
#pragma unroll
            for (int ii = 0; ii < 8; ii++)
                sm[WUQ_S + (lt * 8 + ii) * 153 + h] = acc[ii];
        }
        __syncthreads();
        if (tid < 150) {
            sm[V_S + tid]  = v0[b * 150 + tid];
            sm[VB_S + tid] = Vmat[b * 150 + tid];
        }
        __syncthreads();
        if (tid < 80) {
            float x0 = (2 * tid     < 150) ? sm[V_S + 2 * tid]     : 0.f;
            float x1 = (2 * tid + 1 < 150) ? sm[V_S + 2 * tid + 1] : 0.f;
            vpair[tid] = pack2(x0, x1);
        }
        if (tid >= 128 && tid < 133) ccpair[75 + tid - 128] = 0u;
        if (tid >= 160 && tid < 180) rgpair[300 + tid - 160] = 0u;
    }
    __syncthreads();

    // ======== main scan: 128 steps, block-local ========
    for (int i = 0; i < LPn; i++) {
        // ---- Stage A: staging loads (registers) + wv (w0-7) + gh (w8-31) ----
        float stg = 0.f;
        if (tid < 900) {
            if (tid < 150)      stg = Up[(i * Bn + b) * 150 + tid];
            else if (tid < 300) stg = d_wup[(b * LPn + i) * 150 + tid - 150];
            else                stg = d_gu[(b * LPn + i) * 600 + tid - 300];
        }
        if (w < 8) {
            int kg = w >> 2, jgl = w & 3;
            float d[5][4];
#pragma unroll
            for (int t = 0; t < 5; t++) { d[t][0]=d[t][1]=d[t][2]=d[t][3]=0.f; }
            gemv_acc<5>(d, g_WvPk, WV_NJT, kg * 5, kg * 5 + 5, jgl * 5, vpair, ln);
            store_part<5>(d, sm + WVP_S + kg * 160, jgl * 5, ln);
        } else {
            int wl = w - 8;                 // 0..23
            int kg = wl / 12, jgl = wl - kg * 12;
            float d[5][4];
#pragma unroll
            for (int t = 0; t < 5; t++) { d[t][0]=d[t][1]=d[t][2]=d[t][3]=0.f; }
            gemv_acc<5>(d, g_WhhPk, WHH_NJT, kg * 5, kg * 5 + 5, jgl * 5, vpair, ln);
            store_part<5>(d, sm + GHP_S + kg * 480, jgl * 5, ln);
        }
        // store staged values (loads have had the whole MMA stage to land)
        if (tid < 150)      sm[U_S + tid] = stg;
        else if (tid < 300) sm[BSE_S + tid - 150] = stg;
        else if (tid < 900) sm[GU_S + tid - 300] = stg;
        __syncthreads();
        // ---- combine: bse (150) + gh (450) ----
        if (tid < 600) {
            if (tid < 150) {
                sm[BSE_S + tid] += sm[WVP_S + tid] + sm[WVP_S + 160 + tid];
            } else {
                int j = tid - 150;
                sm[GH_S + j] = b_hh[j] + sm[GHP_S + j] + sm[GHP_S + 480 + j];
            }
        }
        __syncthreads();
        // ---- S3: s[l] partials (128 l x 8 k-groups) ----
        {
            int l = tid & 127, g = tid >> 7;
            int k0 = (g * 150) >> 3, k1 = ((g + 1) * 150) >> 3;
            const float* wq = sm + WUQ_S + l * 153;
            float acc = 0.f;
#pragma unroll 10
            for (int k = k0; k < k1; k++)
                acc += tanh_fastest(sm[BSE_S + k] + wq[k]) * sm[VB_S + k];
            sm[AP_S + g * 128 + l] = acc;
        }
        __syncthreads();
        // ---- softmax (warp 0) ----
        if (w == 0) {
            float a0 = 0.f, a1 = 0.f, a2 = 0.f, a3 = 0.f;
#pragma unroll
            for (int g = 0; g < 8; g++) {
                const float* apg = sm + AP_S + g * 128;
                a0 += apg[ln]; a1 += apg[32 + ln]; a2 += apg[64 + ln]; a3 += apg[96 + ln];
            }
            float m = fmaxf(fmaxf(a0, a1), fmaxf(a2, a3));
            m = warp_max_all(m);
            float e0 = __expf(a0 - m), e1 = __expf(a1 - m);
            float e2 = __expf(a2 - m), e3 = __expf(a3 - m);
            float ssum = warp_sum_all(e0 + e1 + e2 + e3);
            float inv = __fdividef(1.0f, ssum);
            sm[A_S + ln] = e0 * inv; sm[A_S + 32 + ln] = e1 * inv;
            sm[A_S + 64 + ln] = e2 * inv; sm[A_S + 96 + ln] = e3 * inv;
        }
        __syncthreads();
        // ---- cc partials (8 l-groups x 150 d) ----
        for (int t = tid; t < 1200; t += NTHR) {
            int lq = t / 150, d = t - lq * 150;
            const __half* uq = UQH + lq * 16 * 152 + d;
            const float* av = sm + A_S + lq * 16;
            float acc = 0.f;
#pragma unroll
            for (int q = 0; q < 16; q++) acc += av[q] * __half2float(uq[q * 152]);
            sm[CCP_S + lq * 152 + d] = acc;
        }
        __syncthreads();
        // ---- cc combine (75 thr, 2 cols each) + pairs ----
        if (tid < 75) {
            float c0 = 0.f, c1 = 0.f;
            int d0 = 2 * tid, d1 = d0 + 1;
#pragma unroll
            for (int g = 0; g < 8; g++) {
                c0 += sm[CCP_S + g * 152 + d0];
                c1 += sm[CCP_S + g * 152 + d1];
            }
            sm[CC_S + d0] = c0; sm[CC_S + d1] = c1;
            ccpair[tid] = pack2(c0, c1);
        }
        __syncthreads();
        // ---- B mma (w0-29): bp = cc @ WgC^T partials ----
        if (w < 30) {
            int kg = w / 15, jgl = w - kg * 15;
            float d[5][4];
#pragma unroll
            for (int t = 0; t < 5; t++) { d[t][0]=d[t][1]=d[t][2]=d[t][3]=0.f; }
            gemv_acc<5>(d, g_WgCPk, WGC_NJT, kg * 5, kg * 5 + 5, jgl * 5, ccpair, ln);
            store_part<5>(d, sm + BP_S + kg * 600, jgl * 5, ln);
        }
        __syncthreads();
        // ---- B combine (300 thr, 2 j each): rg pairs ----
        if (tid < 300) {
            float r2[2];
#pragma unroll
            for (int s = 0; s < 2; s++) {
                int j = 2 * tid + s;
                float g = sm[GU_S + j] + sm[BP_S + j] + sm[BP_S + 600 + j];
                float sg = fast_sig(g);
                int km = (j < 150) ? j : (j < 300) ? j - 150 : (j < 450) ? j - 300 : j - 450;
                float rb = (j < 300) ? sm[U_S + km] : sm[CC_S + km];
                r2[s] = sg * rb;
            }
            rgpair[tid] = pack2(r2[0], r2[1]);
        }
        __syncthreads();
        // ---- C mma (all 32): 4 kg x 8 jg, NT=8, chains 10 chunks ----
        {
            int kg = w >> 3, jgl = w & 7;
            float d[8][4];
#pragma unroll
            for (int t = 0; t < 8; t++) { d[t][0]=d[t][1]=d[t][2]=d[t][3]=0.f; }
            gemv_acc8(d, g_WihPk, WIH_NJT, kg * 10, kg * 10 + 10, jgl * 8, rgpair, ln);
            store_part<8>(d, sm + CPP_S + kg * 512, jgl * 8, ln);
        }
        __syncthreads();
        // ---- GRU combine (75 thr, 2 h each) + v pairs ----
        if (tid < 75) {
            float hn2[2];
#pragma unroll
            for (int s = 0; s < 2; s++) {
                int h = 2 * tid + s;
                float ir = b_ih[h], iz = b_ih[150 + h], in_ = b_ih[300 + h];
#pragma unroll
                for (int g = 0; g < 4; g++) {
                    const float* cp = sm + CPP_S + g * 512;
                    ir += cp[h]; iz += cp[150 + h]; in_ += cp[300 + h];
                }
                float r_ = fast_sig(ir + sm[GH_S + h]);
                float z_ = fast_sig(iz + sm[GH_S + 150 + h]);
                float n_ = fast_tanh(in_ + r_ * sm[GH_S + 300 + h]);
                float hnew = (1.0f - z_) * n_ + z_ * sm[V_S + h];
                out[(i * Bn + b) * 150 + h] = hnew;
                sm[V_S + h] = hnew;
                hn2[s] = hnew;
            }
            vpair[tid] = pack2(hn2[0], hn2[1]);
        }
        __syncthreads();
    }
}

// ---------------- launch ----------------
extern "C" void kernel_launch(void* const* d_in, const int* in_sizes, int n_in,
                              void* d_out, int out_size)
{
    const float* Up   = (const float*)d_in[0];
    const float* Uq   = (const float*)d_in[1];
    const float* Wp   = (const float*)d_in[2];
    const float* Wq   = (const float*)d_in[3];
    const float* Wv   = (const float*)d_in[4];
    const float* Wg   = (const float*)d_in[5];
    const float* Vm   = (const float*)d_in[6];
    const float* v0   = (const float*)d_in[7];
    const float* W_ih = (const float*)d_in[8];
    const float* W_hh = (const float*)d_in[9];
    const float* b_ih = (const float*)d_in[10];
    const float* b_hh = (const float*)d_in[11];
    float* out = (float*)d_out;

    cudaFuncSetAttribute(pqm_kernel, cudaFuncAttributeMaxDynamicSharedMemorySize, SMEM_BYTES);
    pqm_kernel<<<NBLK, NTHR, SMEM_BYTES>>>(Up, Uq, Wp, Wq, Wv, Wg, Vm, v0,
                                           W_ih, W_hh, b_ih, b_hh, out);
}